// round 13
// baseline (speedup 1.0000x reference)
#include <cuda_runtime.h>

#define BB 4
#define TK 512
#define TQ 512
#define KS 256     // KEYSIZE == QUESIZE
#define H  128
#define VS 256
#define KR 8       // k-rows per attn block

// scratch for projections (allocation-free rule: __device__ globals)
__device__ float g_kp[BB * TK * H];      // [b][t][h]
__device__ float g_qpT[BB * H * TQ];     // [b][h][t]  (transposed!)

// ---- f32x2 packed helpers (Blackwell) -------------------------------------
__device__ __forceinline__ unsigned long long pk2(float x, float y) {
    unsigned long long r;
    asm("mov.b64 %0, {%1,%2};" : "=l"(r) : "f"(x), "f"(y));
    return r;
}
__device__ __forceinline__ void upk2(unsigned long long v, float& x, float& y) {
    asm("mov.b64 {%0,%1}, %2;" : "=f"(x), "=f"(y) : "l"(v));
}
__device__ __forceinline__ void fma2(unsigned long long& d,
                                     unsigned long long a,
                                     unsigned long long b) {
    asm("fma.rn.f32x2 %0, %1, %2, %0;" : "+l"(d) : "l"(a), "l"(b));
}
__device__ __forceinline__ float tanhap(float x) {
    float r;
    asm("tanh.approx.f32 %0, %1;" : "=f"(r) : "f"(x));
    return r;
}

// ---------------------------------------------------------------------------
// Fused projections, single wave: 128 blocks x 512 threads.
// Block b: rows [16b, 16b+16) of BOTH key and que (K then Q, staged xs reused).
// Thread = (h = tid&127, c-half = (tid>>7)&1, row-half = tid>>8): 8 rows,
// 128 c each, f32x2 FMAs; X broadcast LDS, W coalesced LDG; smem reduce.
// ---------------------------------------------------------------------------
__global__ __launch_bounds__(512) void proj_kernel(
    const float* __restrict__ key, const float* __restrict__ que,
    const float* __restrict__ W_k, const float* __restrict__ b_k,
    const float* __restrict__ W_q, const float* __restrict__ b_q)
{
    __shared__ __align__(16) float xs[16 * KS];     // 16KB X tile
    __shared__ __align__(16) float red[16 * 128];   // 8KB cross-half partials
    __shared__ __align__(16) float Ts[128 * 17];    // 8.5KB Q transpose

    const int tid  = threadIdx.x;          // 0..511
    const int h    = tid & 127;
    const int half = (tid >> 7) & 1;
    const int rh   = tid >> 8;             // row half: rows [8rh, 8rh+8)
    const int row0 = blockIdx.x * 16;      // global row in [0,2048)
    const int c0   = half * 128;

#pragma unroll
    for (int phase = 0; phase < 2; phase++) {
        const bool isK = (phase == 0);
        const float* __restrict__ X = isK ? key : que;
        const float* __restrict__ W = isK ? W_k : W_q;
        const float* __restrict__ bias = isK ? b_k : b_q;

        // stage X tile: 16 rows x 256 cols = 1024 float4, 2 per thread
        __syncthreads();                   // safe reuse of xs across phases
#pragma unroll
        for (int i = 0; i < 2; i++) {
            const int idx = (i * 512 + tid) * 4;
            *(float4*)&xs[idx] = *(const float4*)&X[(size_t)row0 * KS + idx];
        }
        __syncthreads();

        unsigned long long acc2[8];
#pragma unroll
        for (int r = 0; r < 8; r++) acc2[r] = 0ull;

#pragma unroll 8
        for (int cp = 0; cp < 64; cp++) {
            const int c = c0 + 2 * cp;
            const float w0 = W[c * H + h];             // coalesced
            const float w1 = W[(c + 1) * H + h];
            const unsigned long long wu = pk2(w0, w1);
#pragma unroll
            for (int r = 0; r < 8; r++) {
                const float2 x2 = *(const float2*)&xs[(rh * 8 + r) * KS + c];
                fma2(acc2[r], pk2(x2.x, x2.y), wu);
            }
        }

        float acc[8];
#pragma unroll
        for (int r = 0; r < 8; r++) {
            float lo, hi;
            upk2(acc2[r], lo, hi);
            acc[r] = lo + hi;
        }

        // cross-half reduce: half==1 publishes, half==0 finalizes
        if (half == 1) {
#pragma unroll
            for (int r = 0; r < 8; r++)
                red[(rh * 8 + r) * 128 + h] = acc[r];
        }
        __syncthreads();

        if (isK) {
            if (half == 0) {
                const float bb = bias[h];
#pragma unroll
                for (int r = 0; r < 8; r++)
                    g_kp[(row0 + rh * 8 + r) * H + h] =
                        acc[r] + red[(rh * 8 + r) * 128 + h] + bb;
            }
        } else {
            if (half == 0) {
                const float bb = bias[h];
#pragma unroll
                for (int r = 0; r < 8; r++)
                    Ts[h * 17 + rh * 8 + r] =
                        acc[r] + red[(rh * 8 + r) * 128 + h] + bb;
            }
            __syncthreads();
            const int b  = row0 >> 9;
            const int t0 = row0 & 511;
#pragma unroll
            for (int i = 0; i < 4; i++) {
                int idx = i * 512 + tid;   // 0..2047
                int hh = idx >> 4, r = idx & 15;
                g_qpT[((size_t)b * H + hh) * TQ + t0 + r] = Ts[hh * 17 + r];
            }
        }
    }
}

// ---------------------------------------------------------------------------
// Fused scores + masked softmax + attn@value.
// One block = 8 k-rows of one batch. 256 blocks, 512 threads.
// Phase 1: warp -> tile via SMSP-balancing permutation (each SMSP gets
// complementary tile pairs {t, 15-t}); rows sorted by vl desc (live prefix);
// q loaded once per tile into regs (pipelined), reused for all live rows.
// ---------------------------------------------------------------------------
__global__ __launch_bounds__(512, 2) void attn_kernel(
    const float* __restrict__ value,
    const float* __restrict__ w_v,
    const int*   __restrict__ valid_lens,
    float*       __restrict__ out)
{
    __shared__ __align__(16) float kpS[KR][H];        // 4KB (sorted row order)
    __shared__ __align__(16) float wvS[H];            // 512B
    __shared__ __align__(16) float attnS[KR][TQ];     // 16KB
    __shared__ __align__(16) float scr[16 * 64 * 4];  // 16KB (1024 float4)
    __shared__ int vlS[KR], ordS[KR], svlS[KR];
    __shared__ int maxVlS;

    const int tid  = threadIdx.x;          // 0..511
    const int wid  = tid >> 5;             // 0..15
    const int lane = tid & 31;
    const int bid  = blockIdx.x;           // 0..255
    const int b    = bid >> 6;
    const int kt0  = (bid & 63) * KR;

    if (tid < H) wvS[tid] = w_v[tid];
    if (tid == 0) {
        int v[KR], o[KR];
#pragma unroll
        for (int r = 0; r < KR; r++) { v[r] = valid_lens[b * TK + kt0 + r]; o[r] = r; }
#pragma unroll
        for (int i = 1; i < KR; i++) {     // insertion sort desc
            int vv = v[i], oo = o[i], j = i;
            while (j > 0 && v[j - 1] < vv) { v[j] = v[j - 1]; o[j] = o[j - 1]; j--; }
            v[j] = vv; o[j] = oo;
        }
#pragma unroll
        for (int r = 0; r < KR; r++) {
            svlS[r] = v[r]; ordS[r] = o[r]; vlS[o[r]] = v[r];
        }
        maxVlS = v[0];
    }
    __syncthreads();
    // stage kp rows in SORTED order: kpS[ri] = kp row ordS[ri]
#pragma unroll
    for (int i = 0; i < 2; i++) {
        int idx = i * 512 + tid;           // 0..1023
        int ri = idx >> 7, h = idx & 127;
        kpS[ri][h] = g_kp[(b * TK + kt0 + ordS[ri]) * H + h];
    }
    __syncthreads();

    // ---- phase 1: tile-per-warp (SMSP-balanced), q reused across rows ----
    {
        // SMSP s = wid&3 gets tiles {s, 15-s, 7-s, 8+s}: per-SMSP nl sums equal
        const int s = wid & 3, j = wid >> 2;
        const int tile = (j == 0) ? s : (j == 1) ? 15 - s
                       : (j == 2) ? 7 - s : 8 + s;
        const int base = tile * 32;
        int nl = 0;
#pragma unroll
        for (int i = 0; i < KR; i++) nl += (svlS[i] > base);

        if (nl > 0) {
            const int col = base + lane;
            const float* __restrict__ qp0 = g_qpT + (size_t)b * H * TQ + col;

            float acc[KR];
#pragma unroll
            for (int i = 0; i < KR; i++) acc[i] = 0.f;

            float qc[8], qn[8];
#pragma unroll
            for (int j2 = 0; j2 < 8; j2++) qc[j2] = qp0[j2 * TQ];

            for (int hc = 0; hc < H; hc += 8) {
                if (hc + 8 < H) {
#pragma unroll
                    for (int j2 = 0; j2 < 8; j2++) qn[j2] = qp0[(hc + 8 + j2) * TQ];
                }
                const float4 wv0 = *(const float4*)&wvS[hc];
                const float4 wv1 = *(const float4*)&wvS[hc + 4];
#pragma unroll
                for (int ri = 0; ri < KR; ri++) {
                    if (ri < nl) {                    // warp-uniform
                        const float4 k0 = *(const float4*)&kpS[ri][hc];
                        const float4 k1 = *(const float4*)&kpS[ri][hc + 4];
                        float a = acc[ri];
                        a = fmaf(tanhap(k0.x + qc[0]), wv0.x, a);
                        a = fmaf(tanhap(k0.y + qc[1]), wv0.y, a);
                        a = fmaf(tanhap(k0.z + qc[2]), wv0.z, a);
                        a = fmaf(tanhap(k0.w + qc[3]), wv0.w, a);
                        a = fmaf(tanhap(k1.x + qc[4]), wv1.x, a);
                        a = fmaf(tanhap(k1.y + qc[5]), wv1.y, a);
                        a = fmaf(tanhap(k1.z + qc[6]), wv1.z, a);
                        a = fmaf(tanhap(k1.w + qc[7]), wv1.w, a);
                        acc[ri] = a;
                    }
                }
#pragma unroll
                for (int j2 = 0; j2 < 8; j2++) qc[j2] = qn[j2];
            }
#pragma unroll
            for (int ri = 0; ri < KR; ri++)
                if (ri < nl) attnS[ordS[ri]][col] = acc[ri];
        }
    }
    __syncthreads();

    // ---- phase 2: masked softmax, warp w (w<8) owns row w ----
    if (wid < KR) {
        const int row = wid;
        const int vl  = vlS[row];
        float m = -1e30f;
        for (int t = lane; t < vl; t += 32)
            m = fmaxf(m, attnS[row][t]);
#pragma unroll
        for (int o = 16; o; o >>= 1)
            m = fmaxf(m, __shfl_xor_sync(0xffffffffu, m, o));
        float sum = 0.f;
        for (int t = lane; t < TQ; t += 32) {
            float e = (t < vl) ? __expf(attnS[row][t] - m) : 0.f;
            attnS[row][t] = e;
            sum += e;
        }
#pragma unroll
        for (int o = 16; o; o >>= 1)
            sum += __shfl_xor_sync(0xffffffffu, sum, o);
        const float inv = 1.f / sum;
        for (int t = lane; t < vl; t += 32) attnS[row][t] *= inv;
    }
    __syncthreads();

    // ---- phase 3: out[kr][v] = sum_t attn[kr][t] * value[b][t][v] ----
    {
        const int v4  = tid & 63;
        const int grp = tid >> 6;          // 0..7
        const int krq = grp & 1;           // kr base = 4*krq
        const int th  = grp >> 1;          // t quarter
        const int t0  = th * (TQ / 4);
        const int tmaxr = (maxVlS + 3) & ~3;
        const int bound = (t0 + TQ / 4 < tmaxr) ? t0 + TQ / 4 : tmaxr;

        unsigned long long oxy[4], ozw[4];
#pragma unroll
        for (int i = 0; i < 4; i++) { oxy[i] = 0ull; ozw[i] = 0ull; }

        const float4* __restrict__ val4 =
            (const float4*)&value[(size_t)b * TQ * VS];

        for (int t = t0; t < bound; t += 4) {
            float4 a4[4];
#pragma unroll
            for (int i = 0; i < 4; i++)
                a4[i] = *(const float4*)&attnS[4 * krq + i][t];   // broadcast
#pragma unroll
            for (int tt = 0; tt < 4; tt++) {
                const float4 v = val4[(t + tt) * (VS / 4) + v4];
                const unsigned long long vxy = pk2(v.x, v.y);
                const unsigned long long vzw = pk2(v.z, v.w);
#pragma unroll
                for (int i = 0; i < 4; i++) {
                    const float a = (tt == 0) ? a4[i].x :
                                    (tt == 1) ? a4[i].y :
                                    (tt == 2) ? a4[i].z : a4[i].w;
                    const unsigned long long au = pk2(a, a);
                    fma2(oxy[i], au, vxy);
                    fma2(ozw[i], au, vzw);
                }
            }
        }
        __syncthreads();                   // everyone done READING attnS
        float4* p0 = (float4*)&attnS[0][0];     // 1024 float4
        float4* p1 = (float4*)scr;              // 1024 float4
        float4* dst = (th < 2) ? p0 : p1;
        const int sub = th & 1;
#pragma unroll
        for (int i = 0; i < 4; i++) {
            float4 o;
            upk2(oxy[i], o.x, o.y);
            upk2(ozw[i], o.z, o.w);
            dst[(sub * 8 + 4 * krq + i) * 64 + v4] = o;
        }
        __syncthreads();
        {
            const int kr = tid >> 6;       // 0..7
            const int vv = tid & 63;
            float4 r0 = p0[kr * 64 + vv];
            float4 r1 = p0[(8 + kr) * 64 + vv];
            float4 r2 = p1[kr * 64 + vv];
            float4 r3 = p1[(8 + kr) * 64 + vv];
            float4 r = make_float4(r0.x + r1.x + r2.x + r3.x,
                                   r0.y + r1.y + r2.y + r3.y,
                                   r0.z + r1.z + r2.z + r3.z,
                                   r0.w + r1.w + r2.w + r3.w);
            *(float4*)&out[(size_t)(b * TK + kt0 + kr) * VS + vv * 4] = r;
        }
    }
}

// ---------------------------------------------------------------------------
extern "C" void kernel_launch(void* const* d_in, const int* in_sizes, int n_in,
                              void* d_out, int out_size)
{
    const float* key        = (const float*)d_in[0];
    const float* que        = (const float*)d_in[1];
    const float* value      = (const float*)d_in[2];
    const float* W_k        = (const float*)d_in[3];
    const float* b_k        = (const float*)d_in[4];
    const float* W_q        = (const float*)d_in[5];
    const float* b_q        = (const float*)d_in[6];
    const float* w_v        = (const float*)d_in[7];
    // d_in[8] = b_v: unused (softmax shift-invariant)
    const int*   valid_lens = (const int*)d_in[9];
    float* out = (float*)d_out;

    proj_kernel<<<128, 512>>>(key, que, W_k, b_k, W_q, b_q);
    attn_kernel<<<BB * TK / KR, 512>>>(value, w_v, valid_lens, out);
}

// round 14
// speedup vs baseline: 1.0625x; 1.0625x over previous
#include <cuda_runtime.h>

#define BB 4
#define TK 512
#define TQ 512
#define KS 256     // KEYSIZE == QUESIZE
#define H  128
#define VS 256
#define KR 8       // k-rows per attn block

// scratch for projections (allocation-free rule: __device__ globals)
__device__ float g_kp[BB * TK * H];      // [b][t][h]
__device__ float g_qpT[BB * H * TQ];     // [b][h][t]  (transposed!)

// ---- f32x2 packed helpers (Blackwell) -------------------------------------
__device__ __forceinline__ unsigned long long pk2(float x, float y) {
    unsigned long long r;
    asm("mov.b64 %0, {%1,%2};" : "=l"(r) : "f"(x), "f"(y));
    return r;
}
__device__ __forceinline__ void upk2(unsigned long long v, float& x, float& y) {
    asm("mov.b64 {%0,%1}, %2;" : "=f"(x), "=f"(y) : "l"(v));
}
__device__ __forceinline__ void fma2(unsigned long long& d,
                                     unsigned long long a,
                                     unsigned long long b) {
    asm("fma.rn.f32x2 %0, %1, %2, %0;" : "+l"(d) : "l"(a), "l"(b));
}
__device__ __forceinline__ float tanhap(float x) {
    float r;
    asm("tanh.approx.f32 %0, %1;" : "=f"(r) : "f"(x));
    return r;
}

// ---------------------------------------------------------------------------
// Projections, split-K f32x2 (R12 measured-best). 256 threads:
// h = tid&127, c-half = tid>>7. blocks [0,128): kp (row-major out).
// blocks [128,256): qp (transposed out). X tile staged once in smem
// (one barrier); W coalesced LDG; X broadcast LDS.
// ---------------------------------------------------------------------------
__global__ __launch_bounds__(256) void proj_kernel(
    const float* __restrict__ key, const float* __restrict__ que,
    const float* __restrict__ W_k, const float* __restrict__ b_k,
    const float* __restrict__ W_q, const float* __restrict__ b_q)
{
    __shared__ __align__(16) float xs[16 * KS];   // 16KB X tile (reused: reduce)
    __shared__ __align__(16) float Ts[128 * 17];  // 8.5KB Q transpose

    const int tid  = threadIdx.x;          // 0..255
    const int h    = tid & 127;
    const int half = tid >> 7;             // c half: [0,128) or [128,256)
    const bool isK = (blockIdx.x < 128);
    const int row0 = (blockIdx.x & 127) * 16;
    const float* __restrict__ X = isK ? key : que;
    const float* __restrict__ W = isK ? W_k : W_q;
    const float* __restrict__ bias = isK ? b_k : b_q;

    // stage X tile: 16 rows x 256 cols = 4096 contiguous floats
#pragma unroll
    for (int i = 0; i < 4; i++) {
        const int idx = (i * 256 + tid) * 4;
        *(float4*)&xs[idx] = *(const float4*)&X[(size_t)row0 * KS + idx];
    }
    __syncthreads();

    const int c0 = half * 128;
    unsigned long long acc2[16];
#pragma unroll
    for (int r = 0; r < 16; r++) acc2[r] = 0ull;

#pragma unroll 8
    for (int cp = 0; cp < 64; cp++) {
        const int c = c0 + 2 * cp;
        const float w0 = W[c * H + h];             // coalesced
        const float w1 = W[(c + 1) * H + h];
        const unsigned long long wu = pk2(w0, w1);
#pragma unroll
        for (int r = 0; r < 16; r++) {
            const float2 x2 = *(const float2*)&xs[r * KS + c];  // broadcast
            fma2(acc2[r], pk2(x2.x, x2.y), wu);
        }
    }

    float acc[16];
#pragma unroll
    for (int r = 0; r < 16; r++) {
        float lo, hi;
        upk2(acc2[r], lo, hi);
        acc[r] = lo + hi;
    }

    // cross-half reduce through smem (xs reused)
    __syncthreads();
    float* red = xs;                       // [16][128]
    if (half == 1) {
#pragma unroll
        for (int r = 0; r < 16; r++) red[r * 128 + h] = acc[r];
    }
    __syncthreads();

    if (isK) {
        if (half == 0) {
            const float bb = bias[h];
#pragma unroll
            for (int r = 0; r < 16; r++)
                g_kp[(row0 + r) * H + h] = acc[r] + red[r * 128 + h] + bb;
        }
    } else {
        if (half == 0) {
            const float bb = bias[h];
#pragma unroll
            for (int r = 0; r < 16; r++)
                Ts[h * 17 + r] = acc[r] + red[r * 128 + h] + bb;
        }
        __syncthreads();
        const int b  = row0 >> 9;
        const int t0 = row0 & 511;
#pragma unroll
        for (int i = 0; i < 8; i++) {
            int idx = i * 256 + tid;       // 0..2047
            int hh = idx >> 4, r = idx & 15;
            g_qpT[((size_t)b * H + hh) * TQ + t0 + r] = Ts[hh * 17 + r];
        }
    }
}

// ---------------------------------------------------------------------------
// Fused scores + masked softmax + attn@value.  (R13 measured-best)
// One block = 8 k-rows of one batch. 256 blocks, 512 threads.
// Phase 1: warp -> tile via SMSP-balancing permutation (each SMSP gets
// complementary tile pairs); rows sorted by vl desc (live prefix);
// q loaded once per tile into regs (pipelined), reused for all live rows.
// ---------------------------------------------------------------------------
__global__ __launch_bounds__(512, 2) void attn_kernel(
    const float* __restrict__ value,
    const float* __restrict__ w_v,
    const int*   __restrict__ valid_lens,
    float*       __restrict__ out)
{
    __shared__ __align__(16) float kpS[KR][H];        // 4KB (sorted row order)
    __shared__ __align__(16) float wvS[H];            // 512B
    __shared__ __align__(16) float attnS[KR][TQ];     // 16KB
    __shared__ __align__(16) float scr[16 * 64 * 4];  // 16KB (1024 float4)
    __shared__ int vlS[KR], ordS[KR], svlS[KR];
    __shared__ int maxVlS;

    const int tid  = threadIdx.x;          // 0..511
    const int wid  = tid >> 5;             // 0..15
    const int lane = tid & 31;
    const int bid  = blockIdx.x;           // 0..255
    const int b    = bid >> 6;
    const int kt0  = (bid & 63) * KR;

    if (tid < H) wvS[tid] = w_v[tid];
    if (tid == 0) {
        int v[KR], o[KR];
#pragma unroll
        for (int r = 0; r < KR; r++) { v[r] = valid_lens[b * TK + kt0 + r]; o[r] = r; }
#pragma unroll
        for (int i = 1; i < KR; i++) {     // insertion sort desc
            int vv = v[i], oo = o[i], j = i;
            while (j > 0 && v[j - 1] < vv) { v[j] = v[j - 1]; o[j] = o[j - 1]; j--; }
            v[j] = vv; o[j] = oo;
        }
#pragma unroll
        for (int r = 0; r < KR; r++) {
            svlS[r] = v[r]; ordS[r] = o[r]; vlS[o[r]] = v[r];
        }
        maxVlS = v[0];
    }
    __syncthreads();
    // stage kp rows in SORTED order: kpS[ri] = kp row ordS[ri]
#pragma unroll
    for (int i = 0; i < 2; i++) {
        int idx = i * 512 + tid;           // 0..1023
        int ri = idx >> 7, h = idx & 127;
        kpS[ri][h] = g_kp[(b * TK + kt0 + ordS[ri]) * H + h];
    }
    __syncthreads();

    // ---- phase 1: tile-per-warp (SMSP-balanced), q reused across rows ----
    {
        // SMSP s = wid&3 gets tiles {s, 15-s, 7-s, 8+s}: per-SMSP nl sums equal
        const int s = wid & 3, j = wid >> 2;
        const int tile = (j == 0) ? s : (j == 1) ? 15 - s
                       : (j == 2) ? 7 - s : 8 + s;
        const int base = tile * 32;
        int nl = 0;
#pragma unroll
        for (int i = 0; i < KR; i++) nl += (svlS[i] > base);

        if (nl > 0) {
            const int col = base + lane;
            const float* __restrict__ qp0 = g_qpT + (size_t)b * H * TQ + col;

            float acc[KR];
#pragma unroll
            for (int i = 0; i < KR; i++) acc[i] = 0.f;

            float qc[8], qn[8];
#pragma unroll
            for (int j2 = 0; j2 < 8; j2++) qc[j2] = qp0[j2 * TQ];

            for (int hc = 0; hc < H; hc += 8) {
                if (hc + 8 < H) {
#pragma unroll
                    for (int j2 = 0; j2 < 8; j2++) qn[j2] = qp0[(hc + 8 + j2) * TQ];
                }
                const float4 wv0 = *(const float4*)&wvS[hc];
                const float4 wv1 = *(const float4*)&wvS[hc + 4];
#pragma unroll
                for (int ri = 0; ri < KR; ri++) {
                    if (ri < nl) {                    // warp-uniform
                        const float4 k0 = *(const float4*)&kpS[ri][hc];
                        const float4 k1 = *(const float4*)&kpS[ri][hc + 4];
                        float a = acc[ri];
                        a = fmaf(tanhap(k0.x + qc[0]), wv0.x, a);
                        a = fmaf(tanhap(k0.y + qc[1]), wv0.y, a);
                        a = fmaf(tanhap(k0.z + qc[2]), wv0.z, a);
                        a = fmaf(tanhap(k0.w + qc[3]), wv0.w, a);
                        a = fmaf(tanhap(k1.x + qc[4]), wv1.x, a);
                        a = fmaf(tanhap(k1.y + qc[5]), wv1.y, a);
                        a = fmaf(tanhap(k1.z + qc[6]), wv1.z, a);
                        a = fmaf(tanhap(k1.w + qc[7]), wv1.w, a);
                        acc[ri] = a;
                    }
                }
#pragma unroll
                for (int j2 = 0; j2 < 8; j2++) qc[j2] = qn[j2];
            }
#pragma unroll
            for (int ri = 0; ri < KR; ri++)
                if (ri < nl) attnS[ordS[ri]][col] = acc[ri];
        }
    }
    __syncthreads();

    // ---- phase 2: masked softmax, warp w (w<8) owns row w ----
    if (wid < KR) {
        const int row = wid;
        const int vl  = vlS[row];
        float m = -1e30f;
        for (int t = lane; t < vl; t += 32)
            m = fmaxf(m, attnS[row][t]);
#pragma unroll
        for (int o = 16; o; o >>= 1)
            m = fmaxf(m, __shfl_xor_sync(0xffffffffu, m, o));
        float sum = 0.f;
        for (int t = lane; t < TQ; t += 32) {
            float e = (t < vl) ? __expf(attnS[row][t] - m) : 0.f;
            attnS[row][t] = e;
            sum += e;
        }
#pragma unroll
        for (int o = 16; o; o >>= 1)
            sum += __shfl_xor_sync(0xffffffffu, sum, o);
        const float inv = 1.f / sum;
        for (int t = lane; t < vl; t += 32) attnS[row][t] *= inv;
    }
    __syncthreads();

    // ---- phase 3: out[kr][v] = sum_t attn[kr][t] * value[b][t][v] ----
    {
        const int v4  = tid & 63;
        const int grp = tid >> 6;          // 0..7
        const int krq = grp & 1;           // kr base = 4*krq
        const int th  = grp >> 1;          // t quarter
        const int t0  = th * (TQ / 4);
        const int tmaxr = (maxVlS + 3) & ~3;
        const int bound = (t0 + TQ / 4 < tmaxr) ? t0 + TQ / 4 : tmaxr;

        unsigned long long oxy[4], ozw[4];
#pragma unroll
        for (int i = 0; i < 4; i++) { oxy[i] = 0ull; ozw[i] = 0ull; }

        const float4* __restrict__ val4 =
            (const float4*)&value[(size_t)b * TQ * VS];

        for (int t = t0; t < bound; t += 4) {
            float4 a4[4];
#pragma unroll
            for (int i = 0; i < 4; i++)
                a4[i] = *(const float4*)&attnS[4 * krq + i][t];   // broadcast
#pragma unroll
            for (int tt = 0; tt < 4; tt++) {
                const float4 v = val4[(t + tt) * (VS / 4) + v4];
                const unsigned long long vxy = pk2(v.x, v.y);
                const unsigned long long vzw = pk2(v.z, v.w);
#pragma unroll
                for (int i = 0; i < 4; i++) {
                    const float a = (tt == 0) ? a4[i].x :
                                    (tt == 1) ? a4[i].y :
                                    (tt == 2) ? a4[i].z : a4[i].w;
                    const unsigned long long au = pk2(a, a);
                    fma2(oxy[i], au, vxy);
                    fma2(ozw[i], au, vzw);
                }
            }
        }
        __syncthreads();                   // everyone done READING attnS
        float4* p0 = (float4*)&attnS[0][0];     // 1024 float4
        float4* p1 = (float4*)scr;              // 1024 float4
        float4* dst = (th < 2) ? p0 : p1;
        const int sub = th & 1;
#pragma unroll
        for (int i = 0; i < 4; i++) {
            float4 o;
            upk2(oxy[i], o.x, o.y);
            upk2(ozw[i], o.z, o.w);
            dst[(sub * 8 + 4 * krq + i) * 64 + v4] = o;
        }
        __syncthreads();
        {
            const int kr = tid >> 6;       // 0..7
            const int vv = tid & 63;
            float4 r0 = p0[kr * 64 + vv];
            float4 r1 = p0[(8 + kr) * 64 + vv];
            float4 r2 = p1[kr * 64 + vv];
            float4 r3 = p1[(8 + kr) * 64 + vv];
            float4 r = make_float4(r0.x + r1.x + r2.x + r3.x,
                                   r0.y + r1.y + r2.y + r3.y,
                                   r0.z + r1.z + r2.z + r3.z,
                                   r0.w + r1.w + r2.w + r3.w);
            *(float4*)&out[(size_t)(b * TK + kt0 + kr) * VS + vv * 4] = r;
        }
    }
}

// ---------------------------------------------------------------------------
extern "C" void kernel_launch(void* const* d_in, const int* in_sizes, int n_in,
                              void* d_out, int out_size)
{
    const float* key        = (const float*)d_in[0];
    const float* que        = (const float*)d_in[1];
    const float* value      = (const float*)d_in[2];
    const float* W_k        = (const float*)d_in[3];
    const float* b_k        = (const float*)d_in[4];
    const float* W_q        = (const float*)d_in[5];
    const float* b_q        = (const float*)d_in[6];
    const float* w_v        = (const float*)d_in[7];
    // d_in[8] = b_v: unused (softmax shift-invariant)
    const int*   valid_lens = (const int*)d_in[9];
    float* out = (float*)d_out;

    proj_kernel<<<256, 256>>>(key, que, W_k, b_k, W_q, b_q);
    attn_kernel<<<BB * TK / KR, 512>>>(value, w_v, valid_lens, out);
}